// round 14
// baseline (speedup 1.0000x reference)
#include <cuda_runtime.h>
#include <cuda_bf16.h>
#include <math.h>

#define B_ 128
#define L_ 512
#define CIN 48
#define COUT_ 12
#define D_MODEL 256
#define N_LAYER 4
#define D_STATE 64
#define D_CONV 4
#define HEADDIM 64
#define CHUNK 64
#define D_INNER 512
#define NHEADS 8
#define CONV_DIM 640
#define D_IN_PROJ 1160
#define NTOK (B_ * L_)
#define EPS 1e-5f

// ---------------- scratch (static device globals; no runtime alloc) ----------------
__device__ float g_y[NTOK * D_MODEL];
__device__ float g_h[NTOK * D_MODEL];
__device__ float g_zx[NTOK * D_IN_PROJ];
__device__ float g_ssd[NTOK * D_INNER];
__device__ float g_gate[NTOK * D_INNER];

__device__ __forceinline__ float silu_f(float x) { return x / (1.f + expf(-x)); }

__device__ __forceinline__ float warp_sum(float v) {
    #pragma unroll
    for (int o = 16; o; o >>= 1) v += __shfl_xor_sync(0xffffffffu, v, o);
    return v;
}

// ---------------- bf16 split helpers ----------------
__device__ __forceinline__ void split2(float a, float b, unsigned& hi, unsigned& lo) {
    __nv_bfloat16 ha = __float2bfloat16_rn(a);
    __nv_bfloat16 hb = __float2bfloat16_rn(b);
    __nv_bfloat162 h; h.x = ha; h.y = hb;
    __nv_bfloat162 l = __floats2bfloat162_rn(a - __bfloat162float(ha),
                                             b - __bfloat162float(hb));
    hi = *reinterpret_cast<unsigned*>(&h);
    lo = *reinterpret_cast<unsigned*>(&l);
}
__device__ __forceinline__ void mma_bf16(float (&d)[4], const unsigned (&a)[4],
                                         const unsigned (&b)[2]) {
    asm volatile(
        "mma.sync.aligned.m16n8k16.row.col.f32.bf16.bf16.f32 "
        "{%0,%1,%2,%3}, {%4,%5,%6,%7}, {%8,%9}, {%0,%1,%2,%3};\n"
        : "+f"(d[0]), "+f"(d[1]), "+f"(d[2]), "+f"(d[3])
        : "r"(a[0]), "r"(a[1]), "r"(a[2]), "r"(a[3]), "r"(b[0]), "r"(b[1]));
}
__device__ __forceinline__ void ldsm_x4(unsigned (&r)[4], unsigned addr) {
    asm volatile("ldmatrix.sync.aligned.m8n8.x4.shared.b16 {%0,%1,%2,%3}, [%4];"
        : "=r"(r[0]), "=r"(r[1]), "=r"(r[2]), "=r"(r[3]) : "r"(addr));
}

// ---------------- tensor-core GEMM: C[M,N] = A[M,K] @ W[N,K]^T (+res) ----------------
// bf16 split-3, double-buffered, block tile 128x128x16, 8 warps (4x2), warp 32x64.
// B-fragments processed in two 32-col halves to bound register pressure.
#define TBM 128
#define TBN 128
#define TBK 16
#define SA_W 12
__global__ __launch_bounds__(256, 2) void gemm_bf3(
        const float* __restrict__ A, const float* __restrict__ W,
        const float* __restrict__ res, float* __restrict__ C,
        int M, int N, int K) {
    __shared__ unsigned Ah[2][TBM * SA_W], Al[2][TBM * SA_W];
    __shared__ unsigned Wh[2][TBN * SA_W], Wl[2][TBN * SA_W];
    int tid = threadIdx.x;
    int lane = tid & 31, wid = tid >> 5;
    int wm = (wid >> 1) * 32;
    int wn = (wid & 1) * 64;
    int grp = lane >> 2, qk = lane & 3;
    int m0 = blockIdx.y * TBM, n0 = blockIdx.x * TBN;

    int alm = tid >> 1;               // 0..127 row (A and W share mapping)
    int alk = (tid & 1) * 8;          // 0 or 8 floats

    const float* aptr = A + (long)(m0 + alm) * K + alk;
    const float* wptr = (n0 + alm < N) ? (W + (long)(n0 + alm) * K + alk) : nullptr;

    float4 ar0 = *(const float4*)(aptr);
    float4 ar1 = *(const float4*)(aptr + 4);
    float4 wr0 = make_float4(0.f,0.f,0.f,0.f), wr1 = make_float4(0.f,0.f,0.f,0.f);
    if (wptr) { wr0 = *(const float4*)(wptr); wr1 = *(const float4*)(wptr + 4); }

    unsigned sAh0 = (unsigned)__cvta_generic_to_shared(Ah[0]);
    unsigned sAh1 = (unsigned)__cvta_generic_to_shared(Ah[1]);
    unsigned sAl0 = (unsigned)__cvta_generic_to_shared(Al[0]);
    unsigned sAl1 = (unsigned)__cvta_generic_to_shared(Al[1]);
    unsigned sWh0 = (unsigned)__cvta_generic_to_shared(Wh[0]);
    unsigned sWh1 = (unsigned)__cvta_generic_to_shared(Wh[1]);
    unsigned sWl0 = (unsigned)__cvta_generic_to_shared(Wl[0]);
    unsigned sWl1 = (unsigned)__cvta_generic_to_shared(Wl[1]);
    unsigned a_off = (unsigned)((wm + (lane & 15)) * SA_W + (lane >> 4) * 4) * 4u;
    int b_lrow = (lane & 7) + ((lane >> 4) << 3);
    int b_word = ((lane >> 3) & 1) * 4;

    int base = alm * SA_W + (tid & 1) * 4;   // word base for tile stores

    float acc[2][8][4];
    #pragma unroll
    for (int i = 0; i < 2; i++)
        #pragma unroll
        for (int j = 0; j < 8; j++)
            #pragma unroll
            for (int q = 0; q < 4; q++) acc[i][j][q] = 0.f;

    // prologue: fill buffer 0
    {
        unsigned h, l;
        split2(ar0.x, ar0.y, h, l); Ah[0][base + 0] = h; Al[0][base + 0] = l;
        split2(ar0.z, ar0.w, h, l); Ah[0][base + 1] = h; Al[0][base + 1] = l;
        split2(ar1.x, ar1.y, h, l); Ah[0][base + 2] = h; Al[0][base + 2] = l;
        split2(ar1.z, ar1.w, h, l); Ah[0][base + 3] = h; Al[0][base + 3] = l;
        split2(wr0.x, wr0.y, h, l); Wh[0][base + 0] = h; Wl[0][base + 0] = l;
        split2(wr0.z, wr0.w, h, l); Wh[0][base + 1] = h; Wl[0][base + 1] = l;
        split2(wr1.x, wr1.y, h, l); Wh[0][base + 2] = h; Wl[0][base + 2] = l;
        split2(wr1.z, wr1.w, h, l); Wh[0][base + 3] = h; Wl[0][base + 3] = l;
    }
    __syncthreads();

    int nk = K / TBK;
    for (int i = 0; i < nk; i++) {
        if (i + 1 < nk) {
            int k0 = (i + 1) * TBK;
            ar0 = *(const float4*)(aptr + k0);
            ar1 = *(const float4*)(aptr + k0 + 4);
            if (wptr) {
                wr0 = *(const float4*)(wptr + k0);
                wr1 = *(const float4*)(wptr + k0 + 4);
            }
        }
        int buf = i & 1;
        unsigned bAh = buf ? sAh1 : sAh0;
        unsigned bAl = buf ? sAl1 : sAl0;
        unsigned bWh = buf ? sWh1 : sWh0;
        unsigned bWl = buf ? sWl1 : sWl0;

        unsigned fah[2][4], fal[2][4];
        #pragma unroll
        for (int mt = 0; mt < 2; mt++) {
            unsigned off = a_off + (unsigned)(mt * 16 * SA_W) * 4u;
            ldsm_x4(fah[mt], bAh + off);
            ldsm_x4(fal[mt], bAl + off);
        }
        #pragma unroll
        for (int nh = 0; nh < 2; nh++) {
            unsigned fbh[4][2], fbl[4][2];
            #pragma unroll
            for (int nt2 = 0; nt2 < 2; nt2++) {
                unsigned off = (unsigned)((wn + nh * 32 + nt2 * 16 + b_lrow) * SA_W
                                          + b_word) * 4u;
                unsigned t[4];
                ldsm_x4(t, bWh + off);
                fbh[2*nt2][0] = t[0]; fbh[2*nt2][1] = t[1];
                fbh[2*nt2+1][0] = t[2]; fbh[2*nt2+1][1] = t[3];
                ldsm_x4(t, bWl + off);
                fbl[2*nt2][0] = t[0]; fbl[2*nt2][1] = t[1];
                fbl[2*nt2+1][0] = t[2]; fbl[2*nt2+1][1] = t[3];
            }
            #pragma unroll
            for (int mt = 0; mt < 2; mt++)
                #pragma unroll
                for (int nt = 0; nt < 4; nt++) {
                    mma_bf16(acc[mt][nh*4+nt], fah[mt], fbl[nt]);
                    mma_bf16(acc[mt][nh*4+nt], fal[mt], fbh[nt]);
                    mma_bf16(acc[mt][nh*4+nt], fah[mt], fbh[nt]);
                }
        }

        if (i + 1 < nk) {
            int nb = 1 - buf;
            unsigned h, l;
            split2(ar0.x, ar0.y, h, l); Ah[nb][base + 0] = h; Al[nb][base + 0] = l;
            split2(ar0.z, ar0.w, h, l); Ah[nb][base + 1] = h; Al[nb][base + 1] = l;
            split2(ar1.x, ar1.y, h, l); Ah[nb][base + 2] = h; Al[nb][base + 2] = l;
            split2(ar1.z, ar1.w, h, l); Ah[nb][base + 3] = h; Al[nb][base + 3] = l;
            split2(wr0.x, wr0.y, h, l); Wh[nb][base + 0] = h; Wl[nb][base + 0] = l;
            split2(wr0.z, wr0.w, h, l); Wh[nb][base + 1] = h; Wl[nb][base + 1] = l;
            split2(wr1.x, wr1.y, h, l); Wh[nb][base + 2] = h; Wl[nb][base + 2] = l;
            split2(wr1.z, wr1.w, h, l); Wh[nb][base + 3] = h; Wl[nb][base + 3] = l;
            __syncthreads();
        }
    }

    #pragma unroll
    for (int mt = 0; mt < 2; mt++) {
        #pragma unroll
        for (int j = 0; j < 8; j++) {
            int col = n0 + wn + (j >> 2) * 32 + (j & 3) * 8 + qk * 2;
            if (col >= N) continue;
            int row = m0 + wm + mt * 16 + grp;
            long off0 = (long)row * N + col;
            long off1 = (long)(row + 8) * N + col;
            float2 v0 = make_float2(acc[mt][j][0], acc[mt][j][1]);
            float2 v1 = make_float2(acc[mt][j][2], acc[mt][j][3]);
            if (res) {
                float2 r0 = *(const float2*)(res + off0);
                float2 r1 = *(const float2*)(res + off1);
                v0.x += r0.x; v0.y += r0.y;
                v1.x += r1.x; v1.y += r1.y;
            }
            *(float2*)(C + off0) = v0;
            *(float2*)(C + off1) = v1;
        }
    }
}

// ---------------- LayerNorm (warp per token, in place) ----------------
__global__ void ln_kernel(float* __restrict__ y, const float* __restrict__ w,
                          const float* __restrict__ b) {
    long t = (long)(blockIdx.x * (blockDim.x >> 5)) + (threadIdx.x >> 5);
    int lane = threadIdx.x & 31;
    float* row = y + t * D_MODEL;
    float4 v0 = *(const float4*)(row + lane * 8);
    float4 v1 = *(const float4*)(row + lane * 8 + 4);
    float s = v0.x + v0.y + v0.z + v0.w + v1.x + v1.y + v1.z + v1.w;
    float sq = v0.x*v0.x + v0.y*v0.y + v0.z*v0.z + v0.w*v0.w
             + v1.x*v1.x + v1.y*v1.y + v1.z*v1.z + v1.w*v1.w;
    s = warp_sum(s) * (1.f / D_MODEL);
    sq = warp_sum(sq) * (1.f / D_MODEL);
    float r = rsqrtf(sq - s * s + EPS);
    float4 w0 = *(const float4*)(w + lane * 8);
    float4 w1 = *(const float4*)(w + lane * 8 + 4);
    float4 b0 = *(const float4*)(b + lane * 8);
    float4 b1 = *(const float4*)(b + lane * 8 + 4);
    v0.x = (v0.x - s) * r * w0.x + b0.x; v0.y = (v0.y - s) * r * w0.y + b0.y;
    v0.z = (v0.z - s) * r * w0.z + b0.z; v0.w = (v0.w - s) * r * w0.w + b0.w;
    v1.x = (v1.x - s) * r * w1.x + b1.x; v1.y = (v1.y - s) * r * w1.y + b1.y;
    v1.z = (v1.z - s) * r * w1.z + b1.z; v1.w = (v1.w - s) * r * w1.w + b1.w;
    *(float4*)(row + lane * 8) = v0;
    *(float4*)(row + lane * 8 + 4) = v1;
}

// ---------------- RMSNorm (warp per token) ----------------
__global__ void rms_kernel(const float* __restrict__ y, const float* __restrict__ w,
                           float* __restrict__ out) {
    long t = (long)(blockIdx.x * (blockDim.x >> 5)) + (threadIdx.x >> 5);
    int lane = threadIdx.x & 31;
    const float* row = y + t * D_MODEL;
    float4 v0 = *(const float4*)(row + lane * 8);
    float4 v1 = *(const float4*)(row + lane * 8 + 4);
    float sq = v0.x*v0.x + v0.y*v0.y + v0.z*v0.z + v0.w*v0.w
             + v1.x*v1.x + v1.y*v1.y + v1.z*v1.z + v1.w*v1.w;
    sq = warp_sum(sq) * (1.f / D_MODEL);
    float r = rsqrtf(sq + EPS);
    float4 w0 = *(const float4*)(w + lane * 8);
    float4 w1 = *(const float4*)(w + lane * 8 + 4);
    v0.x *= r * w0.x; v0.y *= r * w0.y; v0.z *= r * w0.z; v0.w *= r * w0.w;
    v1.x *= r * w1.x; v1.y *= r * w1.y; v1.z *= r * w1.z; v1.w *= r * w1.w;
    float* orow = out + t * D_MODEL;
    *(float4*)(orow + lane * 8) = v0;
    *(float4*)(orow + lane * 8 + 4) = v1;
}

// ---------------- SSD chunked scan: tensor-core + FUSED depthwise conv ----------
// Conv(width 4)+bias+silu computed inline from zx during tile load; per-thread
// channel is fixed (q = tid & 63) so weights live in registers.
#define SS_W 36
#define SSD_PLANE (64 * SS_W)
#define SSD_SMEM_BYTES ((10 * SSD_PLANE + 256) * 4)
__global__ __launch_bounds__(256)
void ssd_kernel(const float* __restrict__ zx, const float* __restrict__ cw,
                const float* __restrict__ cb,
                const float* __restrict__ dtb, const float* __restrict__ Alog,
                const float* __restrict__ Dp, float* __restrict__ out) {
    extern __shared__ unsigned smw[];
    unsigned* XTh = smw;
    unsigned* XTl = XTh + SSD_PLANE;
    unsigned* Chp = XTl + SSD_PLANE;
    unsigned* Clp = Chp + SSD_PLANE;
    unsigned* BMh = Clp + SSD_PLANE;
    unsigned* BMl = BMh + SSD_PLANE;
    unsigned* BTh = BMl + SSD_PLANE;
    unsigned* BTl = BTh + SSD_PLANE;
    unsigned* STh = BTl + SSD_PLANE;
    unsigned* STl = STh + SSD_PLANE;
    float* acum = (float*)(STl + SSD_PLANE);
    float* dts = acum + 64;
    float* dd  = dts + 64;
    float* eAl = dd + 64;

    __nv_bfloat16* eXTh = (__nv_bfloat16*)XTh;
    __nv_bfloat16* eXTl = (__nv_bfloat16*)XTl;
    __nv_bfloat16* eCh  = (__nv_bfloat16*)Chp;
    __nv_bfloat16* eCl  = (__nv_bfloat16*)Clp;
    __nv_bfloat16* eBMh = (__nv_bfloat16*)BMh;
    __nv_bfloat16* eBMl = (__nv_bfloat16*)BMl;
    __nv_bfloat16* eBTh = (__nv_bfloat16*)BTh;
    __nv_bfloat16* eBTl = (__nv_bfloat16*)BTl;
    __nv_bfloat16* eSTh = (__nv_bfloat16*)STh;
    __nv_bfloat16* eSTl = (__nv_bfloat16*)STl;

    int tid = threadIdx.x;
    int lane = tid & 31, wid = tid >> 5;
    int wr = (wid >> 1) * 16;
    int wc = (wid & 1) * 32;
    int grp = lane >> 2, qk = lane & 3;
    int b = blockIdx.x >> 3, h = blockIdx.x & 7;
    float Ahc = -expf(Alog[h]);
    float dtbh = dtb[h], Dh = Dp[h];

    // fused-conv per-thread constants (q fixed because 256 % 64 == 0)
    int q = tid & 63;
    int chx = h * 64 + q;          // x channel
    int chB = D_INNER + q;         // B channel (512+q)
    int chC = D_INNER + D_STATE + q;
    float wx0 = cw[chx*D_CONV+0], wx1 = cw[chx*D_CONV+1],
          wx2 = cw[chx*D_CONV+2], wx3 = cw[chx*D_CONV+3];
    float wB0 = cw[chB*D_CONV+0], wB1 = cw[chB*D_CONV+1],
          wB2 = cw[chB*D_CONV+2], wB3 = cw[chB*D_CONV+3];
    float wC0 = cw[chC*D_CONV+0], wC1 = cw[chC*D_CONV+1],
          wC2 = cw[chC*D_CONV+2], wC3 = cw[chC*D_CONV+3];
    float bx = cb[chx], bB = cb[chB], bC = cb[chC];
    // zx column offsets
    int ox = D_INNER + chx;        // 512 + h*64 + q
    int oB = D_INNER + D_INNER + q;       // 1024 + q
    int oC = D_INNER + D_INNER + D_STATE + q; // 1088 + q

    unsigned sXTh = (unsigned)__cvta_generic_to_shared(XTh);
    unsigned sXTl = (unsigned)__cvta_generic_to_shared(XTl);
    unsigned sCh  = (unsigned)__cvta_generic_to_shared(Chp);
    unsigned sCl  = (unsigned)__cvta_generic_to_shared(Clp);
    unsigned sBMh = (unsigned)__cvta_generic_to_shared(BMh);
    unsigned sBMl = (unsigned)__cvta_generic_to_shared(BMl);
    unsigned sBTh = (unsigned)__cvta_generic_to_shared(BTh);
    unsigned sBTl = (unsigned)__cvta_generic_to_shared(BTl);
    unsigned sSTh = (unsigned)__cvta_generic_to_shared(STh);
    unsigned sSTl = (unsigned)__cvta_generic_to_shared(STl);
    unsigned aoffA = (unsigned)((lane & 15) * SS_W + (lane >> 4) * 4) * 4u;
    unsigned aoffB = (unsigned)(((lane & 7) + ((lane >> 4) << 3)) * SS_W
                                + ((lane >> 3) & 1) * 4) * 4u;

    for (int i = tid; i < 2 * SSD_PLANE; i += 256) STh[i] = 0u;
    __syncthreads();

    int r0 = wr + grp, r1 = r0 + 8;

    for (int c = 0; c < 8; ++c) {
        long tok0 = (long)b * L_ + c * CHUNK;
        if (tid < 64) {
            float x = zx[(tok0 + tid) * D_IN_PROJ + (D_IN_PROJ - NHEADS) + h] + dtbh;
            float dt = (x > 20.f) ? x : log1pf(expf(x));
            dts[tid] = dt;
            acum[tid] = Ahc * dt;
        }
        __syncthreads();
        if (tid < 32) {
            float v0 = acum[2 * tid], v1 = acum[2 * tid + 1];
            float s = v0 + v1;
            #pragma unroll
            for (int o = 1; o < 32; o <<= 1) {
                float t = __shfl_up_sync(0xffffffffu, s, o);
                if (tid >= o) s += t;
            }
            acum[2 * tid] = s - v1;
            acum[2 * tid + 1] = s;
        }
        __syncthreads();
        if (tid < 64) {
            eAl[tid] = expf(acum[tid]);
            dd[tid] = dts[tid] * expf(acum[63] - acum[tid]);
        }
        __syncthreads();
        // ---- fused conv + silu + bf16 hi/lo tile build ----
        for (int i = tid; i < 4096; i += 256) {
            int l = i >> 6;                 // q = i & 63 == tid & 63 (fixed)
            long tok = tok0 + l;
            int lg = c * CHUNK + l;         // position in sequence
            float xr = bx, br = bB, crr = bC;
            const float* rbase = zx + (tok - 3) * D_IN_PROJ;
            if (lg >= 3) {
                xr  += rbase[ox] * wx0;  br += rbase[oB] * wB0;  crr += rbase[oC] * wC0;
            } else if (lg + 0 >= 3) { /* unreachable */ }
            if (lg >= 2) {
                const float* r1p = rbase + D_IN_PROJ;
                xr += r1p[ox] * wx1; br += r1p[oB] * wB1; crr += r1p[oC] * wC1;
            }
            if (lg >= 1) {
                const float* r2p = rbase + 2 * D_IN_PROJ;
                xr += r2p[ox] * wx2; br += r2p[oB] * wB2; crr += r2p[oC] * wC2;
            }
            {
                const float* r3p = rbase + 3 * D_IN_PROJ;
                xr += r3p[ox] * wx3; br += r3p[oB] * wB3; crr += r3p[oC] * wC3;
            }
            float xv = silu_f(xr);
            float bv = silu_f(br);
            float cv = silu_f(crr);
            __nv_bfloat16 t;
            t = __float2bfloat16_rn(xv);
            eXTh[q * 72 + l] = t;
            eXTl[q * 72 + l] = __float2bfloat16_rn(xv - __bfloat162float(t));
            t = __float2bfloat16_rn(bv);
            eBMh[l * 72 + q] = t;
            eBMl[l * 72 + q] = __float2bfloat16_rn(bv - __bfloat162float(t));
            float bd = bv * dd[l];
            t = __float2bfloat16_rn(bd);
            eBTh[q * 72 + l] = t;
            eBTl[q * 72 + l] = __float2bfloat16_rn(bd - __bfloat162float(t));
            t = __float2bfloat16_rn(cv);
            eCh[l * 72 + q] = t;
            eCl[l * 72 + q] = __float2bfloat16_rn(cv - __bfloat162float(t));
        }
        __syncthreads();
        float g[4][4];
        #pragma unroll
        for (int j = 0; j < 4; j++)
            #pragma unroll
            for (int qq = 0; qq < 4; qq++) g[j][qq] = 0.f;
        #pragma unroll
        for (int kk = 0; kk < 4; kk++) {
            unsigned ah[4], al4[4], t4[4];
            unsigned ab = (unsigned)(wr * SS_W * 4) + aoffA + kk * 32;
            ldsm_x4(ah, sCh + ab);
            ldsm_x4(al4, sCl + ab);
            unsigned bh[4][2], bl[4][2];
            #pragma unroll
            for (int hf = 0; hf < 2; hf++) {
                unsigned bb = (unsigned)((wc + hf * 16) * SS_W * 4) + aoffB + kk * 32;
                ldsm_x4(t4, sBMh + bb);
                bh[hf*2][0]=t4[0]; bh[hf*2][1]=t4[1]; bh[hf*2+1][0]=t4[2]; bh[hf*2+1][1]=t4[3];
                ldsm_x4(t4, sBMl + bb);
                bl[hf*2][0]=t4[0]; bl[hf*2][1]=t4[1]; bl[hf*2+1][0]=t4[2]; bl[hf*2+1][1]=t4[3];
            }
            #pragma unroll
            for (int j = 0; j < 4; j++) {
                mma_bf16(g[j], ah, bl[j]);
                mma_bf16(g[j], al4, bh[j]);
                mma_bf16(g[j], ah, bh[j]);
            }
        }
        __syncthreads();
        {
            float ar0 = acum[r0], ar1 = acum[r1];
            #pragma unroll
            for (int j = 0; j < 4; j++) {
                int cc = wc + j * 8 + qk * 2;
                float as0 = acum[cc], as1 = acum[cc + 1];
                float d0 = dts[cc], d1 = dts[cc + 1];
                float v00 = (cc     <= r0) ? g[j][0] * expf(ar0 - as0) * d0 : 0.f;
                float v01 = (cc + 1 <= r0) ? g[j][1] * expf(ar0 - as1) * d1 : 0.f;
                float v10 = (cc     <= r1) ? g[j][2] * expf(ar1 - as0) * d0 : 0.f;
                float v11 = (cc + 1 <= r1) ? g[j][3] * expf(ar1 - as1) * d1 : 0.f;
                unsigned hi, lo;
                split2(v00, v01, hi, lo);
                BMh[r0 * SS_W + (cc >> 1)] = hi; BMl[r0 * SS_W + (cc >> 1)] = lo;
                split2(v10, v11, hi, lo);
                BMh[r1 * SS_W + (cc >> 1)] = hi; BMl[r1 * SS_W + (cc >> 1)] = lo;
            }
        }
        __syncthreads();
        float ya[4][4], oa[4][4];
        #pragma unroll
        for (int j = 0; j < 4; j++) {
            int cc = wc + j * 8 + qk * 2;
            ya[j][0] = Dh * (__bfloat162float(eXTh[cc * 72 + r0])
                           + __bfloat162float(eXTl[cc * 72 + r0]));
            ya[j][1] = Dh * (__bfloat162float(eXTh[(cc + 1) * 72 + r0])
                           + __bfloat162float(eXTl[(cc + 1) * 72 + r0]));
            ya[j][2] = Dh * (__bfloat162float(eXTh[cc * 72 + r1])
                           + __bfloat162float(eXTl[cc * 72 + r1]));
            ya[j][3] = Dh * (__bfloat162float(eXTh[(cc + 1) * 72 + r1])
                           + __bfloat162float(eXTl[(cc + 1) * 72 + r1]));
            oa[j][0] = oa[j][1] = oa[j][2] = oa[j][3] = 0.f;
        }
        #pragma unroll
        for (int kk = 0; kk < 4; kk++) {
            unsigned ab = (unsigned)(wr * SS_W * 4) + aoffA + kk * 32;
            unsigned mh[4], ml4[4], ch4[4], cl4[4], t4[4];
            ldsm_x4(mh, sBMh + ab); ldsm_x4(ml4, sBMl + ab);
            ldsm_x4(ch4, sCh + ab); ldsm_x4(cl4, sCl + ab);
            unsigned xh[4][2], xl[4][2], shh[4][2], sll[4][2];
            #pragma unroll
            for (int hf = 0; hf < 2; hf++) {
                unsigned bb = (unsigned)((wc + hf * 16) * SS_W * 4) + aoffB + kk * 32;
                ldsm_x4(t4, sXTh + bb);
                xh[hf*2][0]=t4[0]; xh[hf*2][1]=t4[1]; xh[hf*2+1][0]=t4[2]; xh[hf*2+1][1]=t4[3];
                ldsm_x4(t4, sXTl + bb);
                xl[hf*2][0]=t4[0]; xl[hf*2][1]=t4[1]; xl[hf*2+1][0]=t4[2]; xl[hf*2+1][1]=t4[3];
                ldsm_x4(t4, sSTh + bb);
                shh[hf*2][0]=t4[0]; shh[hf*2][1]=t4[1]; shh[hf*2+1][0]=t4[2]; shh[hf*2+1][1]=t4[3];
                ldsm_x4(t4, sSTl + bb);
                sll[hf*2][0]=t4[0]; sll[hf*2][1]=t4[1]; sll[hf*2+1][0]=t4[2]; sll[hf*2+1][1]=t4[3];
            }
            #pragma unroll
            for (int j = 0; j < 4; j++) {
                mma_bf16(ya[j], mh, xl[j]);
                mma_bf16(ya[j], ml4, xh[j]);
                mma_bf16(ya[j], mh, xh[j]);
                mma_bf16(oa[j], ch4, sll[j]);
                mma_bf16(oa[j], cl4, shh[j]);
                mma_bf16(oa[j], ch4, shh[j]);
            }
        }
        {
            float e0 = eAl[r0], e1 = eAl[r1];
            #pragma unroll
            for (int j = 0; j < 4; j++) {
                int cc = wc + j * 8 + qk * 2;
                float* o0 = out + (tok0 + r0) * D_INNER + h * 64 + cc;
                float* o1 = out + (tok0 + r1) * D_INNER + h * 64 + cc;
                *(float2*)o0 = make_float2(ya[j][0] + e0 * oa[j][0],
                                           ya[j][1] + e0 * oa[j][1]);
                *(float2*)o1 = make_float2(ya[j][2] + e1 * oa[j][2],
                                           ya[j][3] + e1 * oa[j][3]);
            }
        }
        __syncthreads();
        {
            float eT = eAl[63];
            float sa[4][4];
            #pragma unroll
            for (int j = 0; j < 4; j++) {
                int cc = wc + j * 8 + qk * 2;
                sa[j][0] = eT * (__bfloat162float(eSTh[r0 * 72 + cc])
                               + __bfloat162float(eSTl[r0 * 72 + cc]));
                sa[j][1] = eT * (__bfloat162float(eSTh[r0 * 72 + cc + 1])
                               + __bfloat162float(eSTl[r0 * 72 + cc + 1]));
                sa[j][2] = eT * (__bfloat162float(eSTh[r1 * 72 + cc])
                               + __bfloat162float(eSTl[r1 * 72 + cc]));
                sa[j][3] = eT * (__bfloat162float(eSTh[r1 * 72 + cc + 1])
                               + __bfloat162float(eSTl[r1 * 72 + cc + 1]));
            }
            #pragma unroll
            for (int kk = 0; kk < 4; kk++) {
                unsigned ab = (unsigned)(wr * SS_W * 4) + aoffA + kk * 32;
                unsigned ah[4], al4[4], t4[4];
                ldsm_x4(ah, sXTh + ab);
                ldsm_x4(al4, sXTl + ab);
                unsigned bh[4][2], bl[4][2];
                #pragma unroll
                for (int hf = 0; hf < 2; hf++) {
                    unsigned bb = (unsigned)((wc + hf * 16) * SS_W * 4) + aoffB + kk * 32;
                    ldsm_x4(t4, sBTh + bb);
                    bh[hf*2][0]=t4[0]; bh[hf*2][1]=t4[1]; bh[hf*2+1][0]=t4[2]; bh[hf*2+1][1]=t4[3];
                    ldsm_x4(t4, sBTl + bb);
                    bl[hf*2][0]=t4[0]; bl[hf*2][1]=t4[1]; bl[hf*2+1][0]=t4[2]; bl[hf*2+1][1]=t4[3];
                }
                #pragma unroll
                for (int j = 0; j < 4; j++) {
                    mma_bf16(sa[j], ah, bl[j]);
                    mma_bf16(sa[j], al4, bh[j]);
                    mma_bf16(sa[j], ah, bh[j]);
                }
            }
            #pragma unroll
            for (int j = 0; j < 4; j++) {
                int cc = wc + j * 8 + qk * 2;
                unsigned hi, lo;
                split2(sa[j][0], sa[j][1], hi, lo);
                STh[r0 * SS_W + (cc >> 1)] = hi; STl[r0 * SS_W + (cc >> 1)] = lo;
                split2(sa[j][2], sa[j][3], hi, lo);
                STh[r1 * SS_W + (cc >> 1)] = hi; STl[r1 * SS_W + (cc >> 1)] = lo;
            }
        }
        __syncthreads();
    }
}

// ---------------- gated RMSNorm (warp per token): rmsnorm(y*silu(z)) * gw ----------
__global__ void gated_kernel(const float* __restrict__ yin, const float* __restrict__ zx,
                             const float* __restrict__ gw, float* __restrict__ out) {
    long t = (long)(blockIdx.x * (blockDim.x >> 5)) + (threadIdx.x >> 5);
    int lane = threadIdx.x & 31;
    const float* yrow = yin + t * D_INNER;
    const float* zrow = zx + t * D_IN_PROJ;
    float u[16];
    float sq = 0.f;
    #pragma unroll
    for (int j = 0; j < 4; j++) {
        int d = lane * 4 + j * 128;
        float4 yv = *(const float4*)(yrow + d);
        float4 zv = *(const float4*)(zrow + d);
        float a0 = yv.x * silu_f(zv.x);
        float a1 = yv.y * silu_f(zv.y);
        float a2 = yv.z * silu_f(zv.z);
        float a3 = yv.w * silu_f(zv.w);
        u[j*4+0] = a0; u[j*4+1] = a1; u[j*4+2] = a2; u[j*4+3] = a3;
        sq += a0*a0 + a1*a1 + a2*a2 + a3*a3;
    }
    sq = warp_sum(sq) * (1.f / D_INNER);
    float r = rsqrtf(sq + EPS);
    float* orow = out + t * D_INNER;
    #pragma unroll
    for (int j = 0; j < 4; j++) {
        int d = lane * 4 + j * 128;
        float4 g = *(const float4*)(gw + d);
        float4 v = make_float4(u[j*4+0]*r*g.x, u[j*4+1]*r*g.y,
                               u[j*4+2]*r*g.z, u[j*4+3]*r*g.w);
        *(float4*)(orow + d) = v;
    }
}

// ---------------- final: rmsnorm(last token) -> elu -> @ out_W^T ----------------
__global__ void final_kernel(const float* __restrict__ y, const float* __restrict__ nw,
                             const float* __restrict__ ow, float* __restrict__ out) {
    __shared__ float sh[8];
    __shared__ float u[256];
    int b = blockIdx.x;
    int d = threadIdx.x;
    float v = y[((long)b * L_ + (L_ - 1)) * D_MODEL + d];
    float sq = v * v;
    #pragma unroll
    for (int o = 16; o; o >>= 1) sq += __shfl_xor_sync(0xffffffffu, sq, o);
    if ((d & 31) == 0) sh[d >> 5] = sq;
    __syncthreads();
    float ms = 0.f;
    #pragma unroll
    for (int i = 0; i < 8; i++) ms += sh[i];
    ms *= (1.f / D_MODEL);
    float x = v * rsqrtf(ms + EPS) * nw[d];
    u[d] = (x > 0.f) ? x : (expf(x) - 1.f);
    __syncthreads();
    if (d < COUT_) {
        float a = 0.f;
        for (int k = 0; k < D_MODEL; k++) a += u[k] * ow[d * D_MODEL + k];
        out[b * COUT_ + d] = a;
    }
}

// ---------------- host orchestration ----------------
extern "C" void kernel_launch(void* const* d_in, const int* in_sizes, int n_in,
                              void* d_out, int out_size) {
    const float* obs     = (const float*)d_in[0];
    const float* in_W    = (const float*)d_in[1];
    const float* ln1_w   = (const float*)d_in[2];
    const float* ln1_b   = (const float*)d_in[3];
    const float* rms_w   = (const float*)d_in[4];
    const float* inproj  = (const float*)d_in[5];
    const float* conv_w  = (const float*)d_in[6];
    const float* conv_b  = (const float*)d_in[7];
    const float* dt_bias = (const float*)d_in[8];
    const float* A_log   = (const float*)d_in[9];
    const float* Dp      = (const float*)d_in[10];
    const float* gnorm   = (const float*)d_in[11];
    const float* outproj = (const float*)d_in[12];
    const float* normf   = (const float*)d_in[13];
    const float* out_W   = (const float*)d_in[14];
    float* out = (float*)d_out;

    float *y, *h, *zx, *ssd, *gate;
    cudaGetSymbolAddress((void**)&y, g_y);
    cudaGetSymbolAddress((void**)&h, g_h);
    cudaGetSymbolAddress((void**)&zx, g_zx);
    cudaGetSymbolAddress((void**)&ssd, g_ssd);
    cudaGetSymbolAddress((void**)&gate, g_gate);

    cudaFuncSetAttribute(ssd_kernel, cudaFuncAttributeMaxDynamicSharedMemorySize,
                         SSD_SMEM_BYTES);

    // 1) y = obs @ in_W^T, then LayerNorm in place
    {
        dim3 grid((D_MODEL + TBN - 1) / TBN, NTOK / TBM);
        gemm_bf3<<<grid, 256>>>(obs, in_W, nullptr, y, NTOK, D_MODEL, CIN);
        ln_kernel<<<NTOK / 8, 256>>>(y, ln1_w, ln1_b);
    }

    for (int i = 0; i < N_LAYER; i++) {
        const float* Wi = inproj + (long)i * D_IN_PROJ * D_MODEL;
        const float* Wo = outproj + (long)i * D_MODEL * D_INNER;
        const float* cwi = conv_w + (long)i * CONV_DIM * D_CONV;
        const float* cbi = conv_b + (long)i * CONV_DIM;
        const float* dtbi = dt_bias + i * NHEADS;
        const float* Ali = A_log + i * NHEADS;
        const float* Dpi = Dp + i * NHEADS;
        const float* gwi = gnorm + (long)i * D_INNER;
        const float* rwi = rms_w + (long)i * D_MODEL;

        rms_kernel<<<NTOK / 8, 256>>>(y, rwi, h);
        {
            dim3 grid((D_IN_PROJ + TBN - 1) / TBN, NTOK / TBM);
            gemm_bf3<<<grid, 256>>>(h, Wi, nullptr, zx, NTOK, D_IN_PROJ, D_MODEL);
        }
        ssd_kernel<<<B_ * NHEADS, 256, SSD_SMEM_BYTES>>>(zx, cwi, cbi,
                                                         dtbi, Ali, Dpi, ssd);
        gated_kernel<<<NTOK / 8, 256>>>(ssd, zx, gwi, gate);
        {
            dim3 grid((D_MODEL + TBN - 1) / TBN, NTOK / TBM);
            gemm_bf3<<<grid, 256>>>(gate, Wo, y, y, NTOK, D_MODEL, D_INNER);
        }
    }

    final_kernel<<<B_, 256>>>(y, normf, out_W, out);
}

// round 15
// speedup vs baseline: 1.4655x; 1.4655x over previous
#include <cuda_runtime.h>
#include <cuda_bf16.h>
#include <math.h>

#define B_ 128
#define L_ 512
#define CIN 48
#define COUT_ 12
#define D_MODEL 256
#define N_LAYER 4
#define D_STATE 64
#define D_CONV 4
#define HEADDIM 64
#define CHUNK 64
#define D_INNER 512
#define NHEADS 8
#define CONV_DIM 640
#define D_IN_PROJ 1160
#define NTOK (B_ * L_)
#define EPS 1e-5f

// ---------------- scratch (static device globals; no runtime alloc) ----------------
__device__ float g_y[NTOK * D_MODEL];
__device__ float g_h[NTOK * D_MODEL];
__device__ float g_zx[NTOK * D_IN_PROJ];
__device__ float g_conv[NTOK * CONV_DIM];
__device__ float g_ssd[NTOK * D_INNER];
__device__ float g_gate[NTOK * D_INNER];

__device__ __forceinline__ float silu_f(float x) { return x / (1.f + expf(-x)); }

__device__ __forceinline__ float warp_sum(float v) {
    #pragma unroll
    for (int o = 16; o; o >>= 1) v += __shfl_xor_sync(0xffffffffu, v, o);
    return v;
}

// ---------------- bf16 split helpers ----------------
__device__ __forceinline__ void split2(float a, float b, unsigned& hi, unsigned& lo) {
    __nv_bfloat16 ha = __float2bfloat16_rn(a);
    __nv_bfloat16 hb = __float2bfloat16_rn(b);
    __nv_bfloat162 h; h.x = ha; h.y = hb;
    __nv_bfloat162 l = __floats2bfloat162_rn(a - __bfloat162float(ha),
                                             b - __bfloat162float(hb));
    hi = *reinterpret_cast<unsigned*>(&h);
    lo = *reinterpret_cast<unsigned*>(&l);
}
__device__ __forceinline__ void mma_bf16(float (&d)[4], const unsigned (&a)[4],
                                         const unsigned (&b)[2]) {
    asm volatile(
        "mma.sync.aligned.m16n8k16.row.col.f32.bf16.bf16.f32 "
        "{%0,%1,%2,%3}, {%4,%5,%6,%7}, {%8,%9}, {%0,%1,%2,%3};\n"
        : "+f"(d[0]), "+f"(d[1]), "+f"(d[2]), "+f"(d[3])
        : "r"(a[0]), "r"(a[1]), "r"(a[2]), "r"(a[3]), "r"(b[0]), "r"(b[1]));
}
__device__ __forceinline__ void ldsm_x4(unsigned (&r)[4], unsigned addr) {
    asm volatile("ldmatrix.sync.aligned.m8n8.x4.shared.b16 {%0,%1,%2,%3}, [%4];"
        : "=r"(r[0]), "=r"(r[1]), "=r"(r[2]), "=r"(r[3]) : "r"(addr));
}

// ---------------- tensor-core GEMM: C[M,N] = A[M,K] @ W[N,K]^T (+res) ----------------
// bf16 split-3, double-buffered, block tile 128x128x16, 8 warps (4x2), warp 32x64.
#define TBM 128
#define TBN 128
#define TBK 16
#define SA_W 12
__global__ __launch_bounds__(256, 2) void gemm_bf3(
        const float* __restrict__ A, const float* __restrict__ W,
        const float* __restrict__ res, float* __restrict__ C,
        int M, int N, int K) {
    __shared__ unsigned Ah[2][TBM * SA_W], Al[2][TBM * SA_W];
    __shared__ unsigned Wh[2][TBN * SA_W], Wl[2][TBN * SA_W];
    int tid = threadIdx.x;
    int lane = tid & 31, wid = tid >> 5;
    int wm = (wid >> 1) * 32;
    int wn = (wid & 1) * 64;
    int grp = lane >> 2, qk = lane & 3;
    int m0 = blockIdx.y * TBM, n0 = blockIdx.x * TBN;

    int alm = tid >> 1;
    int alk = (tid & 1) * 8;

    const float* aptr = A + (long)(m0 + alm) * K + alk;
    const float* wptr = (n0 + alm < N) ? (W + (long)(n0 + alm) * K + alk) : nullptr;

    float4 ar0 = *(const float4*)(aptr);
    float4 ar1 = *(const float4*)(aptr + 4);
    float4 wr0 = make_float4(0.f,0.f,0.f,0.f), wr1 = make_float4(0.f,0.f,0.f,0.f);
    if (wptr) { wr0 = *(const float4*)(wptr); wr1 = *(const float4*)(wptr + 4); }

    unsigned sAh0 = (unsigned)__cvta_generic_to_shared(Ah[0]);
    unsigned sAh1 = (unsigned)__cvta_generic_to_shared(Ah[1]);
    unsigned sAl0 = (unsigned)__cvta_generic_to_shared(Al[0]);
    unsigned sAl1 = (unsigned)__cvta_generic_to_shared(Al[1]);
    unsigned sWh0 = (unsigned)__cvta_generic_to_shared(Wh[0]);
    unsigned sWh1 = (unsigned)__cvta_generic_to_shared(Wh[1]);
    unsigned sWl0 = (unsigned)__cvta_generic_to_shared(Wl[0]);
    unsigned sWl1 = (unsigned)__cvta_generic_to_shared(Wl[1]);
    unsigned a_off = (unsigned)((wm + (lane & 15)) * SA_W + (lane >> 4) * 4) * 4u;
    int b_lrow = (lane & 7) + ((lane >> 4) << 3);
    int b_word = ((lane >> 3) & 1) * 4;

    int base = alm * SA_W + (tid & 1) * 4;

    float acc[2][8][4];
    #pragma unroll
    for (int i = 0; i < 2; i++)
        #pragma unroll
        for (int j = 0; j < 8; j++)
            #pragma unroll
            for (int q = 0; q < 4; q++) acc[i][j][q] = 0.f;

    {
        unsigned h, l;
        split2(ar0.x, ar0.y, h, l); Ah[0][base + 0] = h; Al[0][base + 0] = l;
        split2(ar0.z, ar0.w, h, l); Ah[0][base + 1] = h; Al[0][base + 1] = l;
        split2(ar1.x, ar1.y, h, l); Ah[0][base + 2] = h; Al[0][base + 2] = l;
        split2(ar1.z, ar1.w, h, l); Ah[0][base + 3] = h; Al[0][base + 3] = l;
        split2(wr0.x, wr0.y, h, l); Wh[0][base + 0] = h; Wl[0][base + 0] = l;
        split2(wr0.z, wr0.w, h, l); Wh[0][base + 1] = h; Wl[0][base + 1] = l;
        split2(wr1.x, wr1.y, h, l); Wh[0][base + 2] = h; Wl[0][base + 2] = l;
        split2(wr1.z, wr1.w, h, l); Wh[0][base + 3] = h; Wl[0][base + 3] = l;
    }
    __syncthreads();

    int nk = K / TBK;
    for (int i = 0; i < nk; i++) {
        if (i + 1 < nk) {
            int k0 = (i + 1) * TBK;
            ar0 = *(const float4*)(aptr + k0);
            ar1 = *(const float4*)(aptr + k0 + 4);
            if (wptr) {
                wr0 = *(const float4*)(wptr + k0);
                wr1 = *(const float4*)(wptr + k0 + 4);
            }
        }
        int buf = i & 1;
        unsigned bAh = buf ? sAh1 : sAh0;
        unsigned bAl = buf ? sAl1 : sAl0;
        unsigned bWh = buf ? sWh1 : sWh0;
        unsigned bWl = buf ? sWl1 : sWl0;

        unsigned fah[2][4], fal[2][4];
        #pragma unroll
        for (int mt = 0; mt < 2; mt++) {
            unsigned off = a_off + (unsigned)(mt * 16 * SA_W) * 4u;
            ldsm_x4(fah[mt], bAh + off);
            ldsm_x4(fal[mt], bAl + off);
        }
        #pragma unroll
        for (int nh = 0; nh < 2; nh++) {
            unsigned fbh[4][2], fbl[4][2];
            #pragma unroll
            for (int nt2 = 0; nt2 < 2; nt2++) {
                unsigned off = (unsigned)((wn + nh * 32 + nt2 * 16 + b_lrow) * SA_W
                                          + b_word) * 4u;
                unsigned t[4];
                ldsm_x4(t, bWh + off);
                fbh[2*nt2][0] = t[0]; fbh[2*nt2][1] = t[1];
                fbh[2*nt2+1][0] = t[2]; fbh[2*nt2+1][1] = t[3];
                ldsm_x4(t, bWl + off);
                fbl[2*nt2][0] = t[0]; fbl[2*nt2][1] = t[1];
                fbl[2*nt2+1][0] = t[2]; fbl[2*nt2+1][1] = t[3];
            }
            #pragma unroll
            for (int mt = 0; mt < 2; mt++)
                #pragma unroll
                for (int nt = 0; nt < 4; nt++) {
                    mma_bf16(acc[mt][nh*4+nt], fah[mt], fbl[nt]);
                    mma_bf16(acc[mt][nh*4+nt], fal[mt], fbh[nt]);
                    mma_bf16(acc[mt][nh*4+nt], fah[mt], fbh[nt]);
                }
        }

        if (i + 1 < nk) {
            int nb = 1 - buf;
            unsigned h, l;
            split2(ar0.x, ar0.y, h, l); Ah[nb][base + 0] = h; Al[nb][base + 0] = l;
            split2(ar0.z, ar0.w, h, l); Ah[nb][base + 1] = h; Al[nb][base + 1] = l;
            split2(ar1.x, ar1.y, h, l); Ah[nb][base + 2] = h; Al[nb][base + 2] = l;
            split2(ar1.z, ar1.w, h, l); Ah[nb][base + 3] = h; Al[nb][base + 3] = l;
            split2(wr0.x, wr0.y, h, l); Wh[nb][base + 0] = h; Wl[nb][base + 0] = l;
            split2(wr0.z, wr0.w, h, l); Wh[nb][base + 1] = h; Wl[nb][base + 1] = l;
            split2(wr1.x, wr1.y, h, l); Wh[nb][base + 2] = h; Wl[nb][base + 2] = l;
            split2(wr1.z, wr1.w, h, l); Wh[nb][base + 3] = h; Wl[nb][base + 3] = l;
            __syncthreads();
        }
    }

    #pragma unroll
    for (int mt = 0; mt < 2; mt++) {
        #pragma unroll
        for (int j = 0; j < 8; j++) {
            int col = n0 + wn + (j >> 2) * 32 + (j & 3) * 8 + qk * 2;
            if (col >= N) continue;
            int row = m0 + wm + mt * 16 + grp;
            long off0 = (long)row * N + col;
            long off1 = (long)(row + 8) * N + col;
            float2 v0 = make_float2(acc[mt][j][0], acc[mt][j][1]);
            float2 v1 = make_float2(acc[mt][j][2], acc[mt][j][3]);
            if (res) {
                float2 r0 = *(const float2*)(res + off0);
                float2 r1 = *(const float2*)(res + off1);
                v0.x += r0.x; v0.y += r0.y;
                v1.x += r1.x; v1.y += r1.y;
            }
            *(float2*)(C + off0) = v0;
            *(float2*)(C + off1) = v1;
        }
    }
}

// ---------------- LayerNorm (warp per token, in place) ----------------
__global__ void ln_kernel(float* __restrict__ y, const float* __restrict__ w,
                          const float* __restrict__ b) {
    long t = (long)(blockIdx.x * (blockDim.x >> 5)) + (threadIdx.x >> 5);
    int lane = threadIdx.x & 31;
    float* row = y + t * D_MODEL;
    float4 v0 = *(const float4*)(row + lane * 8);
    float4 v1 = *(const float4*)(row + lane * 8 + 4);
    float s = v0.x + v0.y + v0.z + v0.w + v1.x + v1.y + v1.z + v1.w;
    float sq = v0.x*v0.x + v0.y*v0.y + v0.z*v0.z + v0.w*v0.w
             + v1.x*v1.x + v1.y*v1.y + v1.z*v1.z + v1.w*v1.w;
    s = warp_sum(s) * (1.f / D_MODEL);
    sq = warp_sum(sq) * (1.f / D_MODEL);
    float r = rsqrtf(sq - s * s + EPS);
    float4 w0 = *(const float4*)(w + lane * 8);
    float4 w1 = *(const float4*)(w + lane * 8 + 4);
    float4 b0 = *(const float4*)(b + lane * 8);
    float4 b1 = *(const float4*)(b + lane * 8 + 4);
    v0.x = (v0.x - s) * r * w0.x + b0.x; v0.y = (v0.y - s) * r * w0.y + b0.y;
    v0.z = (v0.z - s) * r * w0.z + b0.z; v0.w = (v0.w - s) * r * w0.w + b0.w;
    v1.x = (v1.x - s) * r * w1.x + b1.x; v1.y = (v1.y - s) * r * w1.y + b1.y;
    v1.z = (v1.z - s) * r * w1.z + b1.z; v1.w = (v1.w - s) * r * w1.w + b1.w;
    *(float4*)(row + lane * 8) = v0;
    *(float4*)(row + lane * 8 + 4) = v1;
}

// ---------------- RMSNorm (warp per token) ----------------
__global__ void rms_kernel(const float* __restrict__ y, const float* __restrict__ w,
                           float* __restrict__ out) {
    long t = (long)(blockIdx.x * (blockDim.x >> 5)) + (threadIdx.x >> 5);
    int lane = threadIdx.x & 31;
    const float* row = y + t * D_MODEL;
    float4 v0 = *(const float4*)(row + lane * 8);
    float4 v1 = *(const float4*)(row + lane * 8 + 4);
    float sq = v0.x*v0.x + v0.y*v0.y + v0.z*v0.z + v0.w*v0.w
             + v1.x*v1.x + v1.y*v1.y + v1.z*v1.z + v1.w*v1.w;
    sq = warp_sum(sq) * (1.f / D_MODEL);
    float r = rsqrtf(sq + EPS);
    float4 w0 = *(const float4*)(w + lane * 8);
    float4 w1 = *(const float4*)(w + lane * 8 + 4);
    v0.x *= r * w0.x; v0.y *= r * w0.y; v0.z *= r * w0.z; v0.w *= r * w0.w;
    v1.x *= r * w1.x; v1.y *= r * w1.y; v1.z *= r * w1.z; v1.w *= r * w1.w;
    float* orow = out + t * D_MODEL;
    *(float4*)(orow + lane * 8) = v0;
    *(float4*)(orow + lane * 8 + 4) = v1;
}

// ---------------- depthwise causal conv (width 4) + bias + silu, float4 ----------------
#define CONV_G (CONV_DIM / 4)
__global__ void conv_kernel(const float* __restrict__ zx, const float* __restrict__ cw,
                            const float* __restrict__ cb, float* __restrict__ out) {
    long idx = (long)blockIdx.x * blockDim.x + threadIdx.x;
    if (idx >= (long)NTOK * CONV_G) return;
    int cg = (int)(idx % CONV_G);
    int ch = cg * 4;
    long t = idx / CONV_G;
    int l = (int)(t & (L_ - 1));
    long brow = t - l;
    float4 wr0 = *(const float4*)(cw + (ch + 0) * D_CONV);
    float4 wr1 = *(const float4*)(cw + (ch + 1) * D_CONV);
    float4 wr2 = *(const float4*)(cw + (ch + 2) * D_CONV);
    float4 wr3 = *(const float4*)(cw + (ch + 3) * D_CONV);
    float4 a = *(const float4*)(cb + ch);
    #pragma unroll
    for (int k = 0; k < D_CONV; k++) {
        int ls = l + k - (D_CONV - 1);
        if (ls >= 0) {
            float4 x = *(const float4*)(zx + (brow + ls) * D_IN_PROJ + D_INNER + ch);
            const float* w0 = &wr0.x; const float* w1 = &wr1.x;
            const float* w2 = &wr2.x; const float* w3 = &wr3.x;
            a.x += x.x * w0[k]; a.y += x.y * w1[k];
            a.z += x.z * w2[k]; a.w += x.w * w3[k];
        }
    }
    a.x = silu_f(a.x); a.y = silu_f(a.y); a.z = silu_f(a.z); a.w = silu_f(a.w);
    *(float4*)(out + t * CONV_DIM + ch) = a;
}

// ---------------- SSD chunked scan: TENSOR-CORE version (R11/R13 known-good) ------
#define SS_W 36
#define SSD_PLANE (64 * SS_W)
#define SSD_SMEM_BYTES ((10 * SSD_PLANE + 256) * 4)
__global__ __launch_bounds__(256)
void ssd_kernel(const float* __restrict__ conv, const float* __restrict__ zx,
                const float* __restrict__ dtb, const float* __restrict__ Alog,
                const float* __restrict__ Dp, float* __restrict__ out) {
    extern __shared__ unsigned smw[];
    unsigned* XTh = smw;
    unsigned* XTl = XTh + SSD_PLANE;
    unsigned* Chp = XTl + SSD_PLANE;
    unsigned* Clp = Chp + SSD_PLANE;
    unsigned* BMh = Clp + SSD_PLANE;
    unsigned* BMl = BMh + SSD_PLANE;
    unsigned* BTh = BMl + SSD_PLANE;
    unsigned* BTl = BTh + SSD_PLANE;
    unsigned* STh = BTl + SSD_PLANE;
    unsigned* STl = STh + SSD_PLANE;
    float* acum = (float*)(STl + SSD_PLANE);
    float* dts = acum + 64;
    float* dd  = dts + 64;
    float* eAl = dd + 64;

    __nv_bfloat16* eXTh = (__nv_bfloat16*)XTh;
    __nv_bfloat16* eXTl = (__nv_bfloat16*)XTl;
    __nv_bfloat16* eCh  = (__nv_bfloat16*)Chp;
    __nv_bfloat16* eCl  = (__nv_bfloat16*)Clp;
    __nv_bfloat16* eBMh = (__nv_bfloat16*)BMh;
    __nv_bfloat16* eBMl = (__nv_bfloat16*)BMl;
    __nv_bfloat16* eBTh = (__nv_bfloat16*)BTh;
    __nv_bfloat16* eBTl = (__nv_bfloat16*)BTl;
    __nv_bfloat16* eSTh = (__nv_bfloat16*)STh;
    __nv_bfloat16* eSTl = (__nv_bfloat16*)STl;

    int tid = threadIdx.x;
    int lane = tid & 31, wid = tid >> 5;
    int wr = (wid >> 1) * 16;
    int wc = (wid & 1) * 32;
    int grp = lane >> 2, qk = lane & 3;
    int b = blockIdx.x >> 3, h = blockIdx.x & 7;
    float Ahc = -expf(Alog[h]);
    float dtbh = dtb[h], Dh = Dp[h];

    unsigned sXTh = (unsigned)__cvta_generic_to_shared(XTh);
    unsigned sXTl = (unsigned)__cvta_generic_to_shared(XTl);
    unsigned sCh  = (unsigned)__cvta_generic_to_shared(Chp);
    unsigned sCl  = (unsigned)__cvta_generic_to_shared(Clp);
    unsigned sBMh = (unsigned)__cvta_generic_to_shared(BMh);
    unsigned sBMl = (unsigned)__cvta_generic_to_shared(BMl);
    unsigned sBTh = (unsigned)__cvta_generic_to_shared(BTh);
    unsigned sBTl = (unsigned)__cvta_generic_to_shared(BTl);
    unsigned sSTh = (unsigned)__cvta_generic_to_shared(STh);
    unsigned sSTl = (unsigned)__cvta_generic_to_shared(STl);
    unsigned aoffA = (unsigned)((lane & 15) * SS_W + (lane >> 4) * 4) * 4u;
    unsigned aoffB = (unsigned)(((lane & 7) + ((lane >> 4) << 3)) * SS_W
                                + ((lane >> 3) & 1) * 4) * 4u;

    for (int i = tid; i < 2 * SSD_PLANE; i += 256) STh[i] = 0u;
    __syncthreads();

    int r0 = wr + grp, r1 = r0 + 8;

    for (int c = 0; c < 8; ++c) {
        long tok0 = (long)b * L_ + c * CHUNK;
        if (tid < 64) {
            float x = zx[(tok0 + tid) * D_IN_PROJ + (D_IN_PROJ - NHEADS) + h] + dtbh;
            float dt = (x > 20.f) ? x : log1pf(expf(x));
            dts[tid] = dt;
            acum[tid] = Ahc * dt;
        }
        __syncthreads();
        if (tid < 32) {
            float v0 = acum[2 * tid], v1 = acum[2 * tid + 1];
            float s = v0 + v1;
            #pragma unroll
            for (int o = 1; o < 32; o <<= 1) {
                float t = __shfl_up_sync(0xffffffffu, s, o);
                if (tid >= o) s += t;
            }
            acum[2 * tid] = s - v1;
            acum[2 * tid + 1] = s;
        }
        __syncthreads();
        if (tid < 64) {
            eAl[tid] = expf(acum[tid]);
            dd[tid] = dts[tid] * expf(acum[63] - acum[tid]);
        }
        __syncthreads();
        for (int i = tid; i < 4096; i += 256) {
            int l = i >> 6, q = i & 63;
            const float* row = conv + (tok0 + l) * CONV_DIM;
            float xv = row[h * 64 + q];
            float bv = row[D_INNER + q];
            float cv = row[D_INNER + D_STATE + q];
            __nv_bfloat16 t;
            t = __float2bfloat16_rn(xv);
            eXTh[q * 72 + l] = t;
            eXTl[q * 72 + l] = __float2bfloat16_rn(xv - __bfloat162float(t));
            t = __float2bfloat16_rn(bv);
            eBMh[l * 72 + q] = t;
            eBMl[l * 72 + q] = __float2bfloat16_rn(bv - __bfloat162float(t));
            float bd = bv * dd[l];
            t = __float2bfloat16_rn(bd);
            eBTh[q * 72 + l] = t;
            eBTl[q * 72 + l] = __float2bfloat16_rn(bd - __bfloat162float(t));
            t = __float2bfloat16_rn(cv);
            eCh[l * 72 + q] = t;
            eCl[l * 72 + q] = __float2bfloat16_rn(cv - __bfloat162float(t));
        }
        __syncthreads();
        float g[4][4];
        #pragma unroll
        for (int j = 0; j < 4; j++)
            #pragma unroll
            for (int q = 0; q < 4; q++) g[j][q] = 0.f;
        #pragma unroll
        for (int kk = 0; kk < 4; kk++) {
            unsigned ah[4], al4[4], t4[4];
            unsigned ab = (unsigned)(wr * SS_W * 4) + aoffA + kk * 32;
            ldsm_x4(ah, sCh + ab);
            ldsm_x4(al4, sCl + ab);
            unsigned bh[4][2], bl[4][2];
            #pragma unroll
            for (int hf = 0; hf < 2; hf++) {
                unsigned bb = (unsigned)((wc + hf * 16) * SS_W * 4) + aoffB + kk * 32;
                ldsm_x4(t4, sBMh + bb);
                bh[hf*2][0]=t4[0]; bh[hf*2][1]=t4[1]; bh[hf*2+1][0]=t4[2]; bh[hf*2+1][1]=t4[3];
                ldsm_x4(t4, sBMl + bb);
                bl[hf*2][0]=t4[0]; bl[hf*2][1]=t4[1]; bl[hf*2+1][0]=t4[2]; bl[hf*2+1][1]=t4[3];
            }
            #pragma unroll
            for (int j = 0; j < 4; j++) {
                mma_bf16(g[j], ah, bl[j]);
                mma_bf16(g[j], al4, bh[j]);
                mma_bf16(g[j], ah, bh[j]);
            }
        }
        __syncthreads();
        {
            float ar0 = acum[r0], ar1 = acum[r1];
            #pragma unroll
            for (int j = 0; j < 4; j++) {
                int cc = wc + j * 8 + qk * 2;
                float as0 = acum[cc], as1 = acum[cc + 1];
                float d0 = dts[cc], d1 = dts[cc + 1];
                float v00 = (cc     <= r0) ? g[j][0] * expf(ar0 - as0) * d0 : 0.f;
                float v01 = (cc + 1 <= r0) ? g[j][1] * expf(ar0 - as1) * d1 : 0.f;
                float v10 = (cc     <= r1) ? g[j][2] * expf(ar1 - as0) * d0 : 0.f;
                float v11 = (cc + 1 <= r1) ? g[j][3] * expf(ar1 - as1) * d1 : 0.f;
                unsigned hi, lo;
                split2(v00, v01, hi, lo);
                BMh[r0 * SS_W + (cc >> 1)] = hi; BMl[r0 * SS_W + (cc >> 1)] = lo;
                split2(v10, v11, hi, lo);
                BMh[r1 * SS_W + (cc >> 1)] = hi; BMl[r1 * SS_W + (cc >> 1)] = lo;
            }
        }
        __syncthreads();
        float ya[4][4], oa[4][4];
        #pragma unroll
        for (int j = 0; j < 4; j++) {
            int cc = wc + j * 8 + qk * 2;
            ya[j][0] = Dh * (__bfloat162float(eXTh[cc * 72 + r0])
                           + __bfloat162float(eXTl[cc * 72 + r0]));
            ya[j][1] = Dh * (__bfloat162float(eXTh[(cc + 1) * 72 + r0])
                           + __bfloat162float(eXTl[(cc + 1) * 72 + r0]));
            ya[j][2] = Dh * (__bfloat162float(eXTh[cc * 72 + r1])
                           + __bfloat162float(eXTl[cc * 72 + r1]));
            ya[j][3] = Dh * (__bfloat162float(eXTh[(cc + 1) * 72 + r1])
                           + __bfloat162float(eXTl[(cc + 1) * 72 + r1]));
            oa[j][0] = oa[j][1] = oa[j][2] = oa[j][3] = 0.f;
        }
        #pragma unroll
        for (int kk = 0; kk < 4; kk++) {
            unsigned ab = (unsigned)(wr * SS_W * 4) + aoffA + kk * 32;
            unsigned mh[4], ml4[4], ch4[4], cl4[4], t4[4];
            ldsm_x4(mh, sBMh + ab); ldsm_x4(ml4, sBMl + ab);
            ldsm_x4(ch4, sCh + ab); ldsm_x4(cl4, sCl + ab);
            unsigned xh[4][2], xl[4][2], shh[4][2], sll[4][2];
            #pragma unroll
            for (int hf = 0; hf < 2; hf++) {
                unsigned bb = (unsigned)((wc + hf * 16) * SS_W * 4) + aoffB + kk * 32;
                ldsm_x4(t4, sXTh + bb);
                xh[hf*2][0]=t4[0]; xh[hf*2][1]=t4[1]; xh[hf*2+1][0]=t4[2]; xh[hf*2+1][1]=t4[3];
                ldsm_x4(t4, sXTl + bb);
                xl[hf*2][0]=t4[0]; xl[hf*2][1]=t4[1]; xl[hf*2+1][0]=t4[2]; xl[hf*2+1][1]=t4[3];
                ldsm_x4(t4, sSTh + bb);
                shh[hf*2][0]=t4[0]; shh[hf*2][1]=t4[1]; shh[hf*2+1][0]=t4[2]; shh[hf*2+1][1]=t4[3];
                ldsm_x4(t4, sSTl + bb);
                sll[hf*2][0]=t4[0]; sll[hf*2][1]=t4[1]; sll[hf*2+1][0]=t4[2]; sll[hf*2+1][1]=t4[3];
            }
            #pragma unroll
            for (int j = 0; j < 4; j++) {
                mma_bf16(ya[j], mh, xl[j]);
                mma_bf16(ya[j], ml4, xh[j]);
                mma_bf16(ya[j], mh, xh[j]);
                mma_bf16(oa[j], ch4, sll[j]);
                mma_bf16(oa[j], cl4, shh[j]);
                mma_bf16(oa[j], ch4, shh[j]);
            }
        }
        {
            float e0 = eAl[r0], e1 = eAl[r1];
            #pragma unroll
            for (int j = 0; j < 4; j++) {
                int cc = wc + j * 8 + qk * 2;
                float* o0 = out + (tok0 + r0) * D_INNER + h * 64 + cc;
                float* o1 = out + (tok0 + r1) * D_INNER + h * 64 + cc;
                *(float2*)o0 = make_float2(ya[j][0] + e0 * oa[j][0],
                                           ya[j][1] + e0 * oa[j][1]);
                *(float2*)o1 = make_float2(ya[j][2] + e1 * oa[j][2],
                                           ya[j][3] + e1 * oa[j][3]);
            }
        }
        __syncthreads();
        {
            float eT = eAl[63];
            float sa[4][4];
            #pragma unroll
            for (int j = 0; j < 4; j++) {
                int cc = wc + j * 8 + qk * 2;
                sa[j][0] = eT * (__bfloat162float(eSTh[r0 * 72 + cc])
                               + __bfloat162float(eSTl[r0 * 72 + cc]));
                sa[j][1] = eT * (__bfloat162float(eSTh[r0 * 72 + cc + 1])
                               + __bfloat162float(eSTl[r0 * 72 + cc + 1]));
                sa[j][2] = eT * (__bfloat162float(eSTh[r1 * 72 + cc])
                               + __bfloat162float(eSTl[r1 * 72 + cc]));
                sa[j][3] = eT * (__bfloat162float(eSTh[r1 * 72 + cc + 1])
                               + __bfloat162float(eSTl[r1 * 72 + cc + 1]));
            }
            #pragma unroll
            for (int kk = 0; kk < 4; kk++) {
                unsigned ab = (unsigned)(wr * SS_W * 4) + aoffA + kk * 32;
                unsigned ah[4], al4[4], t4[4];
                ldsm_x4(ah, sXTh + ab);
                ldsm_x4(al4, sXTl + ab);
                unsigned bh[4][2], bl[4][2];
                #pragma unroll
                for (int hf = 0; hf < 2; hf++) {
                    unsigned bb = (unsigned)((wc + hf * 16) * SS_W * 4) + aoffB + kk * 32;
                    ldsm_x4(t4, sBTh + bb);
                    bh[hf*2][0]=t4[0]; bh[hf*2][1]=t4[1]; bh[hf*2+1][0]=t4[2]; bh[hf*2+1][1]=t4[3];
                    ldsm_x4(t4, sBTl + bb);
                    bl[hf*2][0]=t4[0]; bl[hf*2][1]=t4[1]; bl[hf*2+1][0]=t4[2]; bl[hf*2+1][1]=t4[3];
                }
                #pragma unroll
                for (int j = 0; j < 4; j++) {
                    mma_bf16(sa[j], ah, bl[j]);
                    mma_bf16(sa[j], al4, bh[j]);
                    mma_bf16(sa[j], ah, bh[j]);
                }
            }
            #pragma unroll
            for (int j = 0; j < 4; j++) {
                int cc = wc + j * 8 + qk * 2;
                unsigned hi, lo;
                split2(sa[j][0], sa[j][1], hi, lo);
                STh[r0 * SS_W + (cc >> 1)] = hi; STl[r0 * SS_W + (cc >> 1)] = lo;
                split2(sa[j][2], sa[j][3], hi, lo);
                STh[r1 * SS_W + (cc >> 1)] = hi; STl[r1 * SS_W + (cc >> 1)] = lo;
            }
        }
        __syncthreads();
    }
}

// ---------------- gated RMSNorm (warp per token): rmsnorm(y*silu(z)) * gw ----------
__global__ void gated_kernel(const float* __restrict__ yin, const float* __restrict__ zx,
                             const float* __restrict__ gw, float* __restrict__ out) {
    long t = (long)(blockIdx.x * (blockDim.x >> 5)) + (threadIdx.x >> 5);
    int lane = threadIdx.x & 31;
    const float* yrow = yin + t * D_INNER;
    const float* zrow = zx + t * D_IN_PROJ;
    float u[16];
    float sq = 0.f;
    #pragma unroll
    for (int j = 0; j < 4; j++) {
        int d = lane * 4 + j * 128;
        float4 yv = *(const float4*)(yrow + d);
        float4 zv = *(const float4*)(zrow + d);
        float a0 = yv.x * silu_f(zv.x);
        float a1 = yv.y * silu_f(zv.y);
        float a2 = yv.z * silu_f(zv.z);
        float a3 = yv.w * silu_f(zv.w);
        u[j*4+0] = a0; u[j*4+1] = a1; u[j*4+2] = a2; u[j*4+3] = a3;
        sq += a0*a0 + a1*a1 + a2*a2 + a3*a3;
    }
    sq = warp_sum(sq) * (1.f / D_INNER);
    float r = rsqrtf(sq + EPS);
    float* orow = out + t * D_INNER;
    #pragma unroll
    for (int j = 0; j < 4; j++) {
        int d = lane * 4 + j * 128;
        float4 g = *(const float4*)(gw + d);
        float4 v = make_float4(u[j*4+0]*r*g.x, u[j*4+1]*r*g.y,
                               u[j*4+2]*r*g.z, u[j*4+3]*r*g.w);
        *(float4*)(orow + d) = v;
    }
}

// ---------------- final: rmsnorm(last token) -> elu -> @ out_W^T ----------------
__global__ void final_kernel(const float* __restrict__ y, const float* __restrict__ nw,
                             const float* __restrict__ ow, float* __restrict__ out) {
    __shared__ float sh[8];
    __shared__ float u[256];
    int b = blockIdx.x;
    int d = threadIdx.x;
    float v = y[((long)b * L_ + (L_ - 1)) * D_MODEL + d];
    float sq = v * v;
    #pragma unroll
    for (int o = 16; o; o >>= 1) sq += __shfl_xor_sync(0xffffffffu, sq, o);
    if ((d & 31) == 0) sh[d >> 5] = sq;
    __syncthreads();
    float ms = 0.f;
    #pragma unroll
    for (int i = 0; i < 8; i++) ms += sh[i];
    ms *= (1.f / D_MODEL);
    float x = v * rsqrtf(ms + EPS) * nw[d];
    u[d] = (x > 0.f) ? x : (expf(x) - 1.f);
    __syncthreads();
    if (d < COUT_) {
        float a = 0.f;
        for (int k = 0; k < D_MODEL; k++) a += u[k] * ow[d * D_MODEL + k];
        out[b * COUT_ + d] = a;
    }
}

// ---------------- host orchestration ----------------
extern "C" void kernel_launch(void* const* d_in, const int* in_sizes, int n_in,
                              void* d_out, int out_size) {
    const float* obs     = (const float*)d_in[0];
    const float* in_W    = (const float*)d_in[1];
    const float* ln1_w   = (const float*)d_in[2];
    const float* ln1_b   = (const float*)d_in[3];
    const float* rms_w   = (const float*)d_in[4];
    const float* inproj  = (const float*)d_in[5];
    const float* conv_w  = (const float*)d_in[6];
    const float* conv_b  = (const float*)d_in[7];
    const float* dt_bias = (const float*)d_in[8];
    const float* A_log   = (const float*)d_in[9];
    const float* Dp      = (const float*)d_in[10];
    const float* gnorm   = (const float*)d_in[11];
    const float* outproj = (const float*)d_in[12];
    const float* normf   = (const float*)d_in[13];
    const float* out_W   = (const float*)d_in[14];
    float* out = (float*)d_out;

    float *y, *h, *zx, *conv, *ssd, *gate;
    cudaGetSymbolAddress((void**)&y, g_y);
    cudaGetSymbolAddress((void**)&h, g_h);
    cudaGetSymbolAddress((void**)&zx, g_zx);
    cudaGetSymbolAddress((void**)&conv, g_conv);
    cudaGetSymbolAddress((void**)&ssd, g_ssd);
    cudaGetSymbolAddress((void**)&gate, g_gate);

    cudaFuncSetAttribute(ssd_kernel, cudaFuncAttributeMaxDynamicSharedMemorySize,
                         SSD_SMEM_BYTES);

    // 1) y = obs @ in_W^T, then LayerNorm in place
    {
        dim3 grid((D_MODEL + TBN - 1) / TBN, NTOK / TBM);
        gemm_bf3<<<grid, 256>>>(obs, in_W, nullptr, y, NTOK, D_MODEL, CIN);
        ln_kernel<<<NTOK / 8, 256>>>(y, ln1_w, ln1_b);
    }

    for (int i = 0; i < N_LAYER; i++) {
        const float* Wi = inproj + (long)i * D_IN_PROJ * D_MODEL;
        const float* Wo = outproj + (long)i * D_MODEL * D_INNER;
        const float* cwi = conv_w + (long)i * CONV_DIM * D_CONV;
        const float* cbi = conv_b + (long)i * CONV_DIM;
        const float* dtbi = dt_bias + i * NHEADS;
        const float* Ali = A_log + i * NHEADS;
        const float* Dpi = Dp + i * NHEADS;
        const float* gwi = gnorm + (long)i * D_INNER;
        const float* rwi = rms_w + (long)i * D_MODEL;

        rms_kernel<<<NTOK / 8, 256>>>(y, rwi, h);
        {
            dim3 grid((D_IN_PROJ + TBN - 1) / TBN, NTOK / TBM);
            gemm_bf3<<<grid, 256>>>(h, Wi, nullptr, zx, NTOK, D_IN_PROJ, D_MODEL);
        }
        {
            long total = (long)NTOK * CONV_G;
            int blocks = (int)((total + 255) / 256);
            conv_kernel<<<blocks, 256>>>(zx, cwi, cbi, conv);
        }
        ssd_kernel<<<B_ * NHEADS, 256, SSD_SMEM_BYTES>>>(conv, zx, dtbi, Ali, Dpi, ssd);
        gated_kernel<<<NTOK / 8, 256>>>(ssd, zx, gwi, gate);
        {
            dim3 grid((D_MODEL + TBN - 1) / TBN, NTOK / TBM);
            gemm_bf3<<<grid, 256>>>(gate, Wo, y, y, NTOK, D_MODEL, D_INNER);
        }
    }

    final_kernel<<<B_, 256>>>(y, normf, out_W, out);
}